// round 10
// baseline (speedup 1.0000x reference)
#include <cuda_runtime.h>
#include <cuda_bf16.h>
#include <math.h>
#include <stdint.h>

#define NEGMIN (-3.4028234663852886e38f)
#define EMB_SCALE 22.627416997969522f
#define LN_EPS 1e-5f

__device__ float g_buf [4*128*32];
__device__ float g_h   [4*128*512];
__device__ float g_qkv [2*512*1536];
__device__ float g_t2  [4*512*512];
__device__ float g_tmp [512*512];
__device__ float g_vbar[4*512];
__device__ float g_pe  [128*512];
__device__ float g_M   [32*2048];
__device__ float g_c1  [2048];
__device__ float g_basev[4*2048];
__device__ __nv_bfloat16 g_hhi [512*512],  g_hlo [512*512];
__device__ __nv_bfloat16 g_athi[512*512],  g_atlo[512*512];
__device__ __nv_bfloat16 g_ffhi[512*2048], g_fflo[512*2048];
__device__ __nv_bfloat16 g_whi[2*3145728];
__device__ __nv_bfloat16 g_wlo[2*3145728];

__device__ __forceinline__ float warp_sum(float v){
    v += __shfl_xor_sync(0xffffffffu, v, 16);
    v += __shfl_xor_sync(0xffffffffu, v, 8);
    v += __shfl_xor_sync(0xffffffffu, v, 4);
    v += __shfl_xor_sync(0xffffffffu, v, 2);
    v += __shfl_xor_sync(0xffffffffu, v, 1);
    return v;
}
__device__ __forceinline__ float warp_max(float v){
    v = fmaxf(v, __shfl_xor_sync(0xffffffffu, v, 16));
    v = fmaxf(v, __shfl_xor_sync(0xffffffffu, v, 8));
    v = fmaxf(v, __shfl_xor_sync(0xffffffffu, v, 4));
    v = fmaxf(v, __shfl_xor_sync(0xffffffffu, v, 2));
    v = fmaxf(v, __shfl_xor_sync(0xffffffffu, v, 1));
    return v;
}
__device__ __forceinline__ float gelu_f(float x){
    float x3 = x*x*x;
    return 0.5f*x*(1.0f + tanhf(0.7978845608028654f*(x + 0.044715f*x3)));
}
static __device__ __forceinline__ uint32_t smem_u32(const void* p){
    uint32_t a;
    asm("{ .reg .u64 t; cvta.to.shared.u64 t, %1; cvt.u32.u64 %0, t; }" : "=r"(a) : "l"(p));
    return a;
}
static __device__ __forceinline__ void ldm4(uint32_t* r, uint32_t addr){
    asm volatile("ldmatrix.sync.aligned.m8n8.x4.shared.b16 {%0,%1,%2,%3}, [%4];"
        : "=r"(r[0]),"=r"(r[1]),"=r"(r[2]),"=r"(r[3]) : "r"(addr));
}
static __device__ __forceinline__ void mma_bf16(float* c, const uint32_t* a, const uint32_t* b){
    asm volatile("mma.sync.aligned.m16n8k16.row.col.f32.bf16.bf16.f32 "
        "{%0,%1,%2,%3}, {%4,%5,%6,%7}, {%8,%9}, {%0,%1,%2,%3};"
        : "+f"(c[0]),"+f"(c[1]),"+f"(c[2]),"+f"(c[3])
        : "r"(a[0]),"r"(a[1]),"r"(a[2]),"r"(a[3]), "r"(b[0]),"r"(b[1]));
}
static __device__ __forceinline__ void cpa16(uint32_t dst, const void* src){
    asm volatile("cp.async.ca.shared.global [%0], [%1], 16;" :: "r"(dst), "l"(src));
}
#define CPA_COMMIT() asm volatile("cp.async.commit_group;" ::: "memory")
#define CPA_WAIT2()  asm volatile("cp.async.wait_group 2;" ::: "memory")
static __device__ __forceinline__ uint32_t b2u(__nv_bfloat162 h){ return *(uint32_t*)&h; }
static __device__ __forceinline__ void split_bf(float v, __nv_bfloat16& hi, __nv_bfloat16& lo){
    hi = __float2bfloat16(v);
    lo = __float2bfloat16(v - __bfloat162float(hi));
}

// ---------- weight split prep (layers 0,1 only) ----------
__global__ void split_weights_kernel(const float* __restrict__ Wq, const float* __restrict__ Wk,
        const float* __restrict__ Wv, const float* __restrict__ Wo,
        const float* __restrict__ W1, const float* __restrict__ W2){
    int i4 = blockIdx.x*blockDim.x + threadIdx.x;
    if (i4 >= 1572864) return;
    int idx = i4*4;
    int l = idx / 3145728;
    int r = idx - l*3145728;
    const float* src;
    if (r < 786432){
        int n = r>>9, k = r&511;
        if (n < 512)       src = Wq + ((size_t)l*512 + n      )*512 + k;
        else if (n < 1024) src = Wk + ((size_t)l*512 + n - 512)*512 + k;
        else               src = Wv + ((size_t)l*512 + n -1024)*512 + k;
    } else if (r < 1048576){
        src = Wo + (size_t)l*262144 + (r - 786432);
    } else if (r < 2097152){
        src = W1 + (size_t)l*1048576 + (r - 1048576);
    } else {
        src = W2 + (size_t)l*1048576 + (r - 2097152);
    }
    float4 v = *(const float4*)src;
    __nv_bfloat162 h0 = __floats2bfloat162_rn(v.x, v.y);
    __nv_bfloat162 h1 = __floats2bfloat162_rn(v.z, v.w);
    __nv_bfloat162 e0 = __floats2bfloat162_rn(v.x - __bfloat162float(h0.x), v.y - __bfloat162float(h0.y));
    __nv_bfloat162 e1 = __floats2bfloat162_rn(v.z - __bfloat162float(h1.x), v.w - __bfloat162float(h1.y));
    *(uint2*)(g_whi + idx) = make_uint2(b2u(h0), b2u(h1));
    *(uint2*)(g_wlo + idx) = make_uint2(b2u(e0), b2u(e1));
}

// ---------- full tensor-core GEMM (layers 0,1) ----------
#define GT_SMEM (3*30720)
template<int MODE>
__global__ __launch_bounds__(256) void gemm_tc(
        const __nv_bfloat16* __restrict__ Ahi, const __nv_bfloat16* __restrict__ Alo,
        const __nv_bfloat16* __restrict__ Whi, const __nv_bfloat16* __restrict__ Wlo,
        const float* __restrict__ bias,
        float* __restrict__ C, __nv_bfloat16* __restrict__ Chi, __nv_bfloat16* __restrict__ Clo,
        int M, int N, int K){
    extern __shared__ char sm[];
    uint32_t sb = smem_u32(sm);
    int tid = threadIdx.x, wid = tid>>5, lane = tid&31;
    int n0 = blockIdx.x*64, m0 = blockIdx.y*128;
    int z = blockIdx.z, nz = gridDim.z;
    int ks = K/nz, kbeg = z*ks, CH = ks/32;
    int wm = (wid>>1)*32, wn = (wid&1)*32;
    float acc[2][4][4];
#pragma unroll
    for (int a = 0; a < 2; a++)
#pragma unroll
        for (int b = 0; b < 4; b++)
#pragma unroll
            for (int c = 0; c < 4; c++) acc[a][b][c] = 0.f;
    uint32_t a_addr = (uint32_t)((wm + (lane&15))*80 + ((lane>>4)<<4));
    uint32_t b_addr = (uint32_t)(20480 + (wn + (lane&7) + ((lane>>4)<<3))*80 + ((lane&8)<<1));
    auto issue_stage = [&](int c){
        if (c < CH){
            uint32_t st = sb + (c%3)*30720;
            int kk = kbeg + c*32;
#pragma unroll
            for (int u = 0; u < 6; u++){
                int i = u*256 + tid;
                uint32_t dst; const __nv_bfloat16* src;
                if (i < 512){
                    int row = i>>2, q = i&3;
                    dst = st + row*80 + q*16;
                    src = Ahi + (size_t)(m0+row)*K + kk + q*8;
                } else if (i < 1024){
                    int i2 = i-512, row = i2>>2, q = i2&3;
                    dst = st + 10240 + row*80 + q*16;
                    src = Alo + (size_t)(m0+row)*K + kk + q*8;
                } else if (i < 1280){
                    int i2 = i-1024, row = i2>>2, q = i2&3;
                    dst = st + 20480 + row*80 + q*16;
                    src = Whi + (size_t)(n0+row)*K + kk + q*8;
                } else {
                    int i2 = i-1280, row = i2>>2, q = i2&3;
                    dst = st + 25600 + row*80 + q*16;
                    src = Wlo + (size_t)(n0+row)*K + kk + q*8;
                }
                cpa16(dst, src);
            }
        }
        CPA_COMMIT();
    };
    issue_stage(0); issue_stage(1); issue_stage(2);
    for (int c = 0; c < CH; c++){
        CPA_WAIT2();
        __syncthreads();
        uint32_t bufb = sb + (c%3)*30720;
#pragma unroll
        for (int s = 0; s < 2; s++){
            uint32_t ah[2][4], al[2][4], bh[2][4], bl[2][4];
            ldm4(ah[0], bufb + a_addr + s*32);
            ldm4(ah[1], bufb + a_addr + 16*80 + s*32);
            ldm4(al[0], bufb + a_addr + 10240 + s*32);
            ldm4(al[1], bufb + a_addr + 10240 + 16*80 + s*32);
            ldm4(bh[0], bufb + b_addr + s*32);
            ldm4(bh[1], bufb + b_addr + 16*80 + s*32);
            ldm4(bl[0], bufb + b_addr + 5120 + s*32);
            ldm4(bl[1], bufb + b_addr + 5120 + 16*80 + s*32);
#pragma unroll
            for (int mt = 0; mt < 2; mt++)
#pragma unroll
                for (int nf = 0; nf < 4; nf++){
                    const uint32_t* Bh = &bh[nf>>1][(nf&1)*2];
                    const uint32_t* Bl = &bl[nf>>1][(nf&1)*2];
                    mma_bf16(acc[mt][nf], ah[mt], Bh);
                    mma_bf16(acc[mt][nf], ah[mt], Bl);
                    mma_bf16(acc[mt][nf], al[mt], Bh);
                }
        }
        __syncthreads();
        issue_stage(c+3);
    }
#pragma unroll
    for (int mt = 0; mt < 2; mt++){
        int r0 = m0 + wm + mt*16 + (lane>>2);
#pragma unroll
        for (int nf = 0; nf < 4; nf++){
            int col = n0 + wn + nf*8 + (lane&3)*2;
            float v0 = acc[mt][nf][0], v1 = acc[mt][nf][1];
            float v2 = acc[mt][nf][2], v3 = acc[mt][nf][3];
            if (MODE == 0){
                size_t zo = (nz > 1) ? (size_t)z*M*N : 0;
                *(float2*)(C + zo + (size_t)r0*N + col)     = make_float2(v0, v1);
                *(float2*)(C + zo + (size_t)(r0+8)*N + col) = make_float2(v2, v3);
            } else {
                float b0 = bias[col], b1 = bias[col+1];
                v0 = gelu_f(v0 + b0); v1 = gelu_f(v1 + b1);
                v2 = gelu_f(v2 + b0); v3 = gelu_f(v3 + b1);
                __nv_bfloat162 h0 = __floats2bfloat162_rn(v0, v1);
                __nv_bfloat162 h2 = __floats2bfloat162_rn(v2, v3);
                __nv_bfloat162 l0 = __floats2bfloat162_rn(v0 - __bfloat162float(h0.x), v1 - __bfloat162float(h0.y));
                __nv_bfloat162 l2 = __floats2bfloat162_rn(v2 - __bfloat162float(h2.x), v3 - __bfloat162float(h2.y));
                *(uint32_t*)(Chi + (size_t)r0*N + col)     = b2u(h0);
                *(uint32_t*)(Chi + (size_t)(r0+8)*N + col) = b2u(h2);
                *(uint32_t*)(Clo + (size_t)r0*N + col)     = b2u(l0);
                *(uint32_t*)(Clo + (size_t)(r0+8)*N + col) = b2u(l2);
            }
        }
    }
}

// ---------- prep ----------
__global__ void init_buf_kernel(const float* __restrict__ hist){
    int idx = blockIdx.x*blockDim.x + threadIdx.x;
    if (idx >= 4*128*32) return;
    int i = idx & 31, t = (idx>>5)&127, b = idx>>12;
    g_buf[idx] = (t < 120) ? hist[(b*120 + t)*32 + i] : 0.0f;
}
__global__ void prep_pe_kernel(){
    int idx = blockIdx.x*blockDim.x + threadIdx.x;
    if (idx >= 128*512) return;
    int d = idx & 511, t = idx>>9;
    double freq = exp((double)(d & ~1) * (-9.210340371976184/512.0));
    double ang = (double)t * freq;
    g_pe[idx] = (float)((d & 1) ? cos(ang) : sin(ang));
}
__global__ __launch_bounds__(256) void prep_M_kernel(const float* __restrict__ Wr1,
        const float* __restrict__ W_emb, const float* __restrict__ b_emb,
        const float* __restrict__ br1){
    int j = blockIdx.x*8 + (threadIdx.x>>5);
    int lane = threadIdx.x&31;
    const float* wr = Wr1 + (size_t)j*1024;
    float a = 0.f;
    for (int k = 0; k < 512; k++) a = fmaf(wr[k], W_emb[k*32 + lane], a);
    g_M[lane*2048 + j] = a * EMB_SCALE;
    float c = 0.f;
    for (int k = lane; k < 512; k += 32) c = fmaf(wr[k], b_emb[k], c);
    c = warp_sum(c);
    if (lane == 0) g_c1[j] = c * EMB_SCALE + br1[j];
}

// ---------- embedding ----------
__global__ __launch_bounds__(512) void embed_kernel(const float* __restrict__ W_emb,
                                                    const float* __restrict__ b_emb){
    __shared__ float xs[32];
    int bt = blockIdx.x, t = bt & 127;
    if (threadIdx.x < 32) xs[threadIdx.x] = g_buf[bt*32 + threadIdx.x];
    __syncthreads();
    int d = threadIdx.x;
    const float* wr = W_emb + d*32;
    float acc = 0.f;
#pragma unroll
    for (int i = 0; i < 32; i++) acc = fmaf(wr[i], xs[i], acc);
    float y = (acc + b_emb[d]) * EMB_SCALE + g_pe[t*512 + d];
    g_h[bt*512 + d] = y;
    __nv_bfloat16 hi, lo; split_bf(y, hi, lo);
    g_hhi[bt*512 + d] = hi; g_hlo[bt*512 + d] = lo;
}

// ---------- full attention (layers 0,1) ----------
__global__ __launch_bounds__(256) void attn_kernel(){
    extern __shared__ float smf[];
    float* kt = smf;
    float* vs = kt + 64*129;
    float* qs = vs + 128*64;
    float* ws = qs + 32*64;
    const float* qp1 = g_qkv + 512*1536;
    int bh = blockIdx.x, b = bh>>3, h = bh&7;
    int q0 = blockIdx.y*32;
    int tid = threadIdx.x;
    for (int idx = tid; idx < 8192; idx += 256){
        int k = idx>>6, d = idx&63;
        int base = (b*128 + k)*1536 + h*64 + d;
        kt[d*129 + k] = g_qkv[base + 512] + qp1[base + 512];
        vs[k*64 + d]  = g_qkv[base + 1024] + qp1[base + 1024];
    }
    for (int idx = tid; idx < 2048; idx += 256){
        int r = idx>>6, d = idx&63;
        int base = (b*128 + q0 + r)*1536 + h*64 + d;
        qs[idx] = g_qkv[base] + qp1[base];
    }
    __syncthreads();
    int warp = tid>>5, lane = tid&31;
    int r0 = warp*4;
    float acc[4][4];
#pragma unroll
    for (int r = 0; r < 4; r++)
#pragma unroll
        for (int s = 0; s < 4; s++) acc[r][s] = 0.f;
#pragma unroll 4
    for (int d = 0; d < 64; d++){
        float k0v = kt[d*129 + lane];
        float k1v = kt[d*129 + 32 + lane];
        float k2v = kt[d*129 + 64 + lane];
        float k3v = kt[d*129 + 96 + lane];
#pragma unroll
        for (int r = 0; r < 4; r++){
            float qv = qs[(r0+r)*64 + d];
            acc[r][0] = fmaf(qv, k0v, acc[r][0]);
            acc[r][1] = fmaf(qv, k1v, acc[r][1]);
            acc[r][2] = fmaf(qv, k2v, acc[r][2]);
            acc[r][3] = fmaf(qv, k3v, acc[r][3]);
        }
    }
#pragma unroll
    for (int r = 0; r < 4; r++){
        int qi = q0 + r0 + r;
        float s[4];
#pragma unroll
        for (int sl = 0; sl < 4; sl++){
            int ki = sl*32 + lane;
            s[sl] = (ki > qi) ? acc[r][sl]*0.125f : NEGMIN;
        }
        float mx = warp_max(fmaxf(fmaxf(s[0], s[1]), fmaxf(s[2], s[3])));
        float e[4], sum = 0.f;
#pragma unroll
        for (int sl = 0; sl < 4; sl++){ e[sl] = expf(s[sl] - mx); sum += e[sl]; }
        sum = warp_sum(sum);
        float inv = 1.0f/sum;
#pragma unroll
        for (int sl = 0; sl < 4; sl++)
            ws[(warp*4 + r)*128 + sl*32 + lane] = e[sl]*inv;
    }
    __syncwarp();
    float o0[4] = {0,0,0,0}, o1[4] = {0,0,0,0};
#pragma unroll 4
    for (int k = 0; k < 128; k++){
        float v0 = vs[k*64 + lane];
        float v1 = vs[k*64 + 32 + lane];
#pragma unroll
        for (int r = 0; r < 4; r++){
            float wv = ws[(warp*4 + r)*128 + k];
            o0[r] = fmaf(wv, v0, o0[r]);
            o1[r] = fmaf(wv, v1, o1[r]);
        }
    }
#pragma unroll
    for (int r = 0; r < 4; r++){
        int row = (b*128 + q0 + r0 + r)*512 + h*64;
        __nv_bfloat16 hi, lo;
        split_bf(o0[r], hi, lo);
        g_athi[row + lane] = hi; g_atlo[row + lane] = lo;
        split_bf(o1[r], hi, lo);
        g_athi[row + 32 + lane] = hi; g_atlo[row + 32 + lane] = lo;
    }
}

// ---------- full LayerNorm ----------
__global__ __launch_bounds__(256) void ln_kernel(float* __restrict__ h,
        const float* __restrict__ parts, const float* __restrict__ bias,
        const float* __restrict__ gw, const float* __restrict__ bw){
    const int MN = 512*512;
    __shared__ float red[8];
    __shared__ float bc;
    int tid = threadIdx.x;
    int base = blockIdx.x*512;
    float x0 = h[base+tid]     + parts[base+tid]     + parts[MN+base+tid]
             + parts[2*MN+base+tid]     + parts[3*MN+base+tid];
    float x1 = h[base+tid+256] + parts[base+tid+256] + parts[MN+base+tid+256]
             + parts[2*MN+base+tid+256] + parts[3*MN+base+tid+256];
    if (bias){ x0 += bias[tid]; x1 += bias[tid+256]; }
    float s = warp_sum(x0 + x1);
    if ((tid&31) == 0) red[tid>>5] = s;
    __syncthreads();
    if (tid == 0){ float t = 0.f; for (int i = 0; i < 8; i++) t += red[i]; bc = t*(1.f/512.f); }
    __syncthreads();
    float mu = bc;
    float d0 = x0 - mu, d1 = x1 - mu;
    float v = warp_sum(d0*d0 + d1*d1);
    if ((tid&31) == 0) red[tid>>5] = v;
    __syncthreads();
    if (tid == 0){ float t = 0.f; for (int i = 0; i < 8; i++) t += red[i]; bc = rsqrtf(t*(1.f/512.f) + LN_EPS); }
    __syncthreads();
    float r = bc;
    float y0 = d0*r*gw[tid]     + bw[tid];
    float y1 = d1*r*gw[tid+256] + bw[tid+256];
    h[base+tid]     = y0;
    h[base+tid+256] = y1;
    __nv_bfloat16 hi, lo;
    split_bf(y0, hi, lo); g_hhi[base+tid] = hi;     g_hlo[base+tid] = lo;
    split_bf(y1, hi, lo); g_hhi[base+tid+256] = hi; g_hlo[base+tid+256] = lo;
}

// ======== SMALL PATH (layers 2,3 — suffix rows only) ========
__global__ __launch_bounds__(512) void hmean_vbar(const float* __restrict__ Wv2){
    __shared__ float hb[512];
    int b = blockIdx.x, tid = threadIdx.x;
    float s = 0.f;
    for (int t = 0; t < 128; t++) s += g_h[(size_t)(b*128+t)*512 + tid];
    hb[tid] = s * (1.f/128.f);
    __syncthreads();
    int w = tid>>5, lane = tid&31;
    const float4* h4 = (const float4*)hb;
    for (int c = w; c < 512; c += 16){
        const float4* w4 = (const float4*)(Wv2 + (size_t)c*512);
        float a = 0.f;
#pragma unroll
        for (int i = 0; i < 4; i++){
            float4 ww = w4[lane + 32*i], hh = h4[lane + 32*i];
            a = fmaf(ww.x, hh.x, a); a = fmaf(ww.y, hh.y, a);
            a = fmaf(ww.z, hh.z, a); a = fmaf(ww.w, hh.w, a);
        }
        a = warp_sum(a);
        if (lane == 0) g_vbar[b*512 + c] = a;
    }
}

__global__ __launch_bounds__(256) void small_gemm512(const float* __restrict__ W,
        const float* __restrict__ bias, int dogelu, const float* __restrict__ In,
        float* __restrict__ Out, int ncols, int outStride, int ps, int nrpb){
    int w = blockIdx.x*8 + (threadIdx.x>>5), lane = threadIdx.x&31;
    int nwarps = gridDim.x*8;
    for (int c = w; c < ncols; c += nwarps){
        const float* wrow = W + (size_t)c*512;
        float4 wr[4];
#pragma unroll
        for (int j = 0; j < 4; j++) wr[j] = *(const float4*)(wrow + 4*(lane + 32*j));
        float bv = bias ? bias[c] : 0.f;
        for (int b = 0; b < 4; b++)
            for (int r = 0; r < nrpb; r++){
                int p = ps + r;
                const float4* in4 = (const float4*)(In + (size_t)(b*128+p)*512);
                float a = 0.f;
#pragma unroll
                for (int j = 0; j < 4; j++){
                    float4 h4 = in4[lane + 32*j];
                    a = fmaf(wr[j].x, h4.x, a); a = fmaf(wr[j].y, h4.y, a);
                    a = fmaf(wr[j].z, h4.z, a); a = fmaf(wr[j].w, h4.w, a);
                }
                a = warp_sum(a);
                if (lane == 0){
                    float v = a + bv;
                    if (dogelu) v = gelu_f(v);
                    Out[(size_t)(b*128+p)*outStride + c] = v;
                }
            }
    }
}

__global__ __launch_bounds__(256) void small_ffn2(const float* __restrict__ W2, int ps, int nrpb){
    int w = blockIdx.x*8 + (threadIdx.x>>5), lane = threadIdx.x&31;
    int nwarps = gridDim.x*8;
    int total = 4*nrpb*512;
    for (int o = w; o < total; o += nwarps){
        int c = o & 511;
        int rr = o >> 9;
        int b = rr / nrpb, p = ps + rr % nrpb;
        const float4* w4 = (const float4*)(W2 + (size_t)c*2048);
        const float4* in4 = (const float4*)(g_t2 + (size_t)(b*128+p)*2048);
        float a = 0.f;
#pragma unroll 4
        for (int i = lane; i < 512; i += 32){
            float4 ww = w4[i], hh = in4[i];
            a = fmaf(ww.x, hh.x, a); a = fmaf(ww.y, hh.y, a);
            a = fmaf(ww.z, hh.z, a); a = fmaf(ww.w, hh.w, a);
        }
        a = warp_sum(a);
        if (lane == 0) g_tmp[(size_t)(b*128+p)*512 + c] = a;
    }
}

__global__ __launch_bounds__(256) void small_attn(int ps, int qcount){
    __shared__ float ks[8][64], vs2[8][64];
    int bh = blockIdx.x, b = bh>>3, h = bh&7;
    int tid = threadIdx.x, wid = tid>>5, lane = tid&31;
    int nk = 127 - ps;
    for (int i = tid; i < nk*64; i += 256){
        int j = i>>6, d = i&63;
        size_t base = (size_t)(b*128 + ps + 1 + j)*1536 + h*64 + d;
        ks[j][d]  = g_qkv[base + 512];
        vs2[j][d] = g_qkv[base + 1024];
    }
    __syncthreads();
    for (int qi = wid; qi < qcount; qi += 8){
        int p = ps + qi;
        size_t orow = (size_t)(b*128+p)*512 + h*64;
        if (p == 127){
            g_t2[orow + lane]      = g_vbar[b*512 + h*64 + lane];
            g_t2[orow + 32 + lane] = g_vbar[b*512 + h*64 + 32 + lane];
            continue;
        }
        float q0 = g_qkv[(size_t)(b*128+p)*1536 + h*64 + lane];
        float q1 = g_qkv[(size_t)(b*128+p)*1536 + h*64 + 32 + lane];
        float sc[8];
        float mx = -1e30f;
#pragma unroll
        for (int j = 0; j < 8; j++){
            if (j >= qi && j < nk){
                float s = warp_sum(q0*ks[j][lane] + q1*ks[j][32+lane]) * 0.125f;
                sc[j] = s;
                mx = fmaxf(mx, s);
            } else sc[j] = -1e30f;
        }
        float e[8], sum = 0.f;
#pragma unroll
        for (int j = 0; j < 8; j++){
            e[j] = (sc[j] > -1e29f) ? expf(sc[j] - mx) : 0.f;
            sum += e[j];
        }
        float inv = 1.f/sum;
        float o0 = 0.f, o1 = 0.f;
#pragma unroll
        for (int j = 0; j < 8; j++){
            o0 = fmaf(e[j]*inv, vs2[j][lane], o0);
            o1 = fmaf(e[j]*inv, vs2[j][32+lane], o1);
        }
        g_t2[orow + lane] = o0;
        g_t2[orow + 32 + lane] = o1;
    }
}

__global__ __launch_bounds__(512) void small_ln(const float* __restrict__ bias,
        const float* __restrict__ gw, const float* __restrict__ bw, int ps, int nrpb){
    __shared__ float red[16];
    __shared__ float bc;
    int blk = blockIdx.x;
    int b = blk / nrpb, p = ps + blk % nrpb;
    int tid = threadIdx.x;
    size_t row = (size_t)(b*128+p)*512;
    float x = g_h[row+tid] + g_tmp[row+tid];
    if (bias) x += bias[tid];
    float s = warp_sum(x);
    if ((tid&31) == 0) red[tid>>5] = s;
    __syncthreads();
    if (tid == 0){ float t = 0.f; for (int i = 0; i < 16; i++) t += red[i]; bc = t*(1.f/512.f); }
    __syncthreads();
    float d = x - bc;
    float v = warp_sum(d*d);
    if ((tid&31) == 0) red[tid>>5] = v;
    __syncthreads();
    if (tid == 0){ float t = 0.f; for (int i = 0; i < 16; i++) t += red[i]; bc = rsqrtf(t*(1.f/512.f) + LN_EPS); }
    __syncthreads();
    g_h[row+tid] = d*bc*gw[tid] + bw[tid];
}

// ---------- refine ----------
__global__ __launch_bounds__(256) void refine_basev(const float* __restrict__ Wr1, int step){
    __shared__ float ctx[512];
    int g = blockIdx.x, b = blockIdx.y;
    int tid = threadIdx.x, warp = tid>>5, lane = tid&31;
    int row = b*128 + 119 + step;
    for (int i = tid; i < 512; i += 256) ctx[i] = g_h[row*512 + i];
    __syncthreads();
#pragma unroll
    for (int r = 0; r < 16; r++){
        int j = g*128 + warp*16 + r;
        const float* wr = Wr1 + (size_t)j*1024 + 512;
        float a = 0.f;
#pragma unroll
        for (int k = lane; k < 512; k += 32) a = fmaf(wr[k], ctx[k], a);
        a = warp_sum(a);
        if (lane == 0) g_basev[b*2048 + j] = a + g_c1[j];
    }
}
__global__ __launch_bounds__(512) void refine_iter(const float* __restrict__ Wr2,
        const float* __restrict__ br2, float* __restrict__ out, int step){
    __shared__ float cur[32];
    __shared__ float basev_s[2048];
    __shared__ float hid[2048];
    __shared__ float outp[32];
    int b = blockIdx.x, tid = threadIdx.x, warp = tid>>5, lane = tid&31;
    int row = b*128 + 119 + step;
    for (int i = tid; i < 2048; i += 512) basev_s[i] = g_basev[b*2048 + i];
    if (tid < 32) cur[tid] = g_buf[row*32 + tid];
    __syncthreads();
    for (int it = 0; it < 5; it++){
#pragma unroll
        for (int c = 0; c < 4; c++){
            int j = c*512 + tid;
            float p = basev_s[j];
#pragma unroll
            for (int k = 0; k < 32; k++) p = fmaf(g_M[k*2048 + j], cur[k], p);
            hid[j] = gelu_f(p);
        }
        __syncthreads();
#pragma unroll
        for (int ii = 0; ii < 2; ii++){
            int i = warp*2 + ii;
            const float* w2 = Wr2 + (size_t)i*2048;
            float p = 0.f;
#pragma unroll 8
            for (int k = lane; k < 2048; k += 32) p = fmaf(w2[k], hid[k], p);
            p = warp_sum(p);
            if (lane == 0) outp[i] = p;
        }
        __syncthreads();
        if (tid < 32) cur[tid] += outp[tid] + br2[tid];
        __syncthreads();
    }
    if (tid < 32){
        float v = cur[tid];
        g_buf[(row+1)*32 + tid] = v;
        out[(b*8 + step)*32 + tid] = v;
    }
}

// ---------- host ----------
#define ATTN_SMEM (22592*4)

extern "C" void kernel_launch(void* const* d_in, const int* in_sizes, int n_in,
                              void* d_out, int out_size){
    const float* hist  = (const float*)d_in[0];
    const float* W_emb = (const float*)d_in[2];
    const float* b_emb = (const float*)d_in[3];
    const float* Wq    = (const float*)d_in[4];
    const float* Wk    = (const float*)d_in[5];
    const float* Wv    = (const float*)d_in[6];
    const float* Wo    = (const float*)d_in[7];
    const float* ln1g  = (const float*)d_in[8];
    const float* ln1b  = (const float*)d_in[9];
    const float* W1    = (const float*)d_in[10];
    const float* b1    = (const float*)d_in[11];
    const float* W2    = (const float*)d_in[12];
    const float* b2    = (const float*)d_in[13];
    const float* ln2g  = (const float*)d_in[14];
    const float* ln2b  = (const float*)d_in[15];
    const float* Wr1   = (const float*)d_in[16];
    const float* br1   = (const float*)d_in[17];
    const float* Wr2   = (const float*)d_in[18];
    const float* br2   = (const float*)d_in[19];
    float* out = (float*)d_out;

    cudaFuncSetAttribute(attn_kernel, cudaFuncAttributeMaxDynamicSharedMemorySize, ATTN_SMEM);
    cudaFuncSetAttribute(gemm_tc<0>, cudaFuncAttributeMaxDynamicSharedMemorySize, GT_SMEM);
    cudaFuncSetAttribute(gemm_tc<1>, cudaFuncAttributeMaxDynamicSharedMemorySize, GT_SMEM);

    float *ph, *pqkv, *pt2, *ptmp;
    __nv_bfloat16 *pwhi, *pwlo, *phhi, *phlo, *pathi, *patlo, *pffhi, *pfflo;
    cudaGetSymbolAddress((void**)&ph,    g_h);
    cudaGetSymbolAddress((void**)&pqkv,  g_qkv);
    cudaGetSymbolAddress((void**)&pt2,   g_t2);
    cudaGetSymbolAddress((void**)&ptmp,  g_tmp);
    cudaGetSymbolAddress((void**)&pwhi,  g_whi);
    cudaGetSymbolAddress((void**)&pwlo,  g_wlo);
    cudaGetSymbolAddress((void**)&phhi,  g_hhi);
    cudaGetSymbolAddress((void**)&phlo,  g_hlo);
    cudaGetSymbolAddress((void**)&pathi, g_athi);
    cudaGetSymbolAddress((void**)&patlo, g_atlo);
    cudaGetSymbolAddress((void**)&pffhi, g_ffhi);
    cudaGetSymbolAddress((void**)&pfflo, g_fflo);

    init_buf_kernel<<<(4*128*32 + 255)/256, 256>>>(hist);
    split_weights_kernel<<<6144, 256>>>(Wq, Wk, Wv, Wo, W1, W2);
    prep_pe_kernel<<<(128*512 + 255)/256, 256>>>();
    prep_M_kernel<<<256, 256>>>(Wr1, W_emb, b_emb, br1);

    for (int step = 0; step < 8; step++){
        int q = 119 + step, nr = 9 - step;
        embed_kernel<<<512, 512>>>(W_emb, b_emb);
        for (int l = 0; l < 2; l++){
            size_t LB = (size_t)l*3145728;
            gemm_tc<0><<<dim3(24,4,2), 256, GT_SMEM>>>(phhi, phlo, pwhi+LB, pwlo+LB,
                    nullptr, pqkv, nullptr, nullptr, 512, 1536, 512);
            attn_kernel<<<dim3(32,4), 256, ATTN_SMEM>>>();
            gemm_tc<0><<<dim3(8,4,4), 256, GT_SMEM>>>(pathi, patlo, pwhi+LB+786432, pwlo+LB+786432,
                    nullptr, pt2, nullptr, nullptr, 512, 512, 512);
            ln_kernel<<<512, 256>>>(ph, pt2, nullptr, ln1g + l*512, ln1b + l*512);
            gemm_tc<1><<<dim3(32,4,1), 256, GT_SMEM>>>(phhi, phlo, pwhi+LB+1048576, pwlo+LB+1048576,
                    b1 + l*2048, nullptr, pffhi, pfflo, 512, 2048, 512);
            gemm_tc<0><<<dim3(8,4,4), 256, GT_SMEM>>>(pffhi, pfflo, pwhi+LB+2097152, pwlo+LB+2097152,
                    nullptr, pt2, nullptr, nullptr, 512, 512, 2048);
            ln_kernel<<<512, 256>>>(ph, pt2, b2 + l*512, ln2g + l*512, ln2b + l*512);
        }
        // small path: layers 2 and 3 on suffix rows q..127
        for (int l = 2; l < 4; l++){
            const float* wq = Wq + (size_t)l*262144;
            const float* wk = Wk + (size_t)l*262144;
            const float* wv = Wv + (size_t)l*262144;
            const float* wo = Wo + (size_t)l*262144;
            const float* w1 = W1 + (size_t)l*1048576;
            const float* w2 = W2 + (size_t)l*1048576;
            int np = (l == 2) ? nr : 1;
            int qc = (l == 2) ? nr : 1;
            if (l == 2) hmean_vbar<<<4, 512>>>(wv);
            small_gemm512<<<64, 256>>>(wq, nullptr, 0, ph, pqkv,        512, 1536, q, nr);
            small_gemm512<<<64, 256>>>(wk, nullptr, 0, ph, pqkv + 512,  512, 1536, q, nr);
            small_gemm512<<<64, 256>>>(wv, nullptr, 0, ph, pqkv + 1024, 512, 1536, q, nr);
            small_attn<<<32, 256>>>(q, qc);
            small_gemm512<<<64, 256>>>(wo, nullptr, 0, pt2, ptmp, 512, 512, q, np);
            small_ln<<<4*np, 512>>>(nullptr, ln1g + l*512, ln1b + l*512, q, np);
            small_gemm512<<<128, 256>>>(w1, b1 + l*2048, 1, ph, pt2, 2048, 2048, q, np);
            small_ffn2<<<128, 256>>>(w2, q, np);
            small_ln<<<4*np, 512>>>(b2 + l*512, ln2g + l*512, ln2b + l*512, q, np);
        }
        refine_basev<<<dim3(16,4), 256>>>(Wr1, step);
        refine_iter<<<4, 512>>>(Wr2, br2, out, step);
    }
}

// round 11
// speedup vs baseline: 1.0624x; 1.0624x over previous
#include <cuda_runtime.h>
#include <cuda_bf16.h>
#include <math.h>
#include <stdint.h>

#define NEGMIN (-3.4028234663852886e38f)
#define EMB_SCALE 22.627416997969522f
#define LN_EPS 1e-5f

__device__ float g_buf [4*128*32];
__device__ float g_h   [4*128*512];
__device__ float g_qkv [2*512*1536];
__device__ float g_t2  [4*512*512];
__device__ float g_tmp [512*512];
__device__ float g_vbar[4*512];
__device__ float g_hbar[4*512];
__device__ float g_pe  [128*512];
__device__ float g_M   [32*2048];
__device__ float g_c1  [2048];
__device__ float g_basev[4*2048];
__device__ __nv_bfloat16 g_hhi [512*512],  g_hlo [512*512];
__device__ __nv_bfloat16 g_athi[512*512],  g_atlo[512*512];
__device__ __nv_bfloat16 g_ffhi[512*2048], g_fflo[512*2048];
__device__ __nv_bfloat16 g_whi[2*3145728];
__device__ __nv_bfloat16 g_wlo[2*3145728];
__device__ unsigned g_bar_cnt;
__device__ volatile unsigned g_bar_gen;

__device__ __forceinline__ float warp_sum(float v){
    v += __shfl_xor_sync(0xffffffffu, v, 16);
    v += __shfl_xor_sync(0xffffffffu, v, 8);
    v += __shfl_xor_sync(0xffffffffu, v, 4);
    v += __shfl_xor_sync(0xffffffffu, v, 2);
    v += __shfl_xor_sync(0xffffffffu, v, 1);
    return v;
}
__device__ __forceinline__ float warp_max(float v){
    v = fmaxf(v, __shfl_xor_sync(0xffffffffu, v, 16));
    v = fmaxf(v, __shfl_xor_sync(0xffffffffu, v, 8));
    v = fmaxf(v, __shfl_xor_sync(0xffffffffu, v, 4));
    v = fmaxf(v, __shfl_xor_sync(0xffffffffu, v, 2));
    v = fmaxf(v, __shfl_xor_sync(0xffffffffu, v, 1));
    return v;
}
__device__ __forceinline__ float gelu_f(float x){
    float x3 = x*x*x;
    return 0.5f*x*(1.0f + tanhf(0.7978845608028654f*(x + 0.044715f*x3)));
}
static __device__ __forceinline__ uint32_t smem_u32(const void* p){
    uint32_t a;
    asm("{ .reg .u64 t; cvta.to.shared.u64 t, %1; cvt.u32.u64 %0, t; }" : "=r"(a) : "l"(p));
    return a;
}
static __device__ __forceinline__ void ldm4(uint32_t* r, uint32_t addr){
    asm volatile("ldmatrix.sync.aligned.m8n8.x4.shared.b16 {%0,%1,%2,%3}, [%4];"
        : "=r"(r[0]),"=r"(r[1]),"=r"(r[2]),"=r"(r[3]) : "r"(addr));
}
static __device__ __forceinline__ void mma_bf16(float* c, const uint32_t* a, const uint32_t* b){
    asm volatile("mma.sync.aligned.m16n8k16.row.col.f32.bf16.bf16.f32 "
        "{%0,%1,%2,%3}, {%4,%5,%6,%7}, {%8,%9}, {%0,%1,%2,%3};"
        : "+f"(c[0]),"+f"(c[1]),"+f"(c[2]),"+f"(c[3])
        : "r"(a[0]),"r"(a[1]),"r"(a[2]),"r"(a[3]), "r"(b[0]),"r"(b[1]));
}
static __device__ __forceinline__ void cpa16(uint32_t dst, const void* src){
    asm volatile("cp.async.ca.shared.global [%0], [%1], 16;" :: "r"(dst), "l"(src));
}
#define CPA_COMMIT() asm volatile("cp.async.commit_group;" ::: "memory")
#define CPA_WAIT2()  asm volatile("cp.async.wait_group 2;" ::: "memory")
static __device__ __forceinline__ uint32_t b2u(__nv_bfloat162 h){ return *(uint32_t*)&h; }
static __device__ __forceinline__ void split_bf(float v, __nv_bfloat16& hi, __nv_bfloat16& lo){
    hi = __float2bfloat16(v);
    lo = __float2bfloat16(v - __bfloat162float(hi));
}
// grid barrier: ticket + monotone generation (survives graph replays)
__device__ __forceinline__ void grid_bar(){
    __threadfence();
    __syncthreads();
    if (threadIdx.x == 0){
        unsigned gen = g_bar_gen;
        unsigned t = atomicAdd(&g_bar_cnt, 1u);
        if (t == gridDim.x - 1){
            g_bar_cnt = 0;
            __threadfence();
            g_bar_gen = gen + 1;
        } else {
            while (g_bar_gen == gen){}
        }
    }
    __syncthreads();
}

// ---------- weight split prep (layers 0,1 only) ----------
__global__ void split_weights_kernel(const float* __restrict__ Wq, const float* __restrict__ Wk,
        const float* __restrict__ Wv, const float* __restrict__ Wo,
        const float* __restrict__ W1, const float* __restrict__ W2){
    int i4 = blockIdx.x*blockDim.x + threadIdx.x;
    if (i4 >= 1572864) return;
    int idx = i4*4;
    int l = idx / 3145728;
    int r = idx - l*3145728;
    const float* src;
    if (r < 786432){
        int n = r>>9, k = r&511;
        if (n < 512)       src = Wq + ((size_t)l*512 + n      )*512 + k;
        else if (n < 1024) src = Wk + ((size_t)l*512 + n - 512)*512 + k;
        else               src = Wv + ((size_t)l*512 + n -1024)*512 + k;
    } else if (r < 1048576){
        src = Wo + (size_t)l*262144 + (r - 786432);
    } else if (r < 2097152){
        src = W1 + (size_t)l*1048576 + (r - 1048576);
    } else {
        src = W2 + (size_t)l*1048576 + (r - 2097152);
    }
    float4 v = *(const float4*)src;
    __nv_bfloat162 h0 = __floats2bfloat162_rn(v.x, v.y);
    __nv_bfloat162 h1 = __floats2bfloat162_rn(v.z, v.w);
    __nv_bfloat162 e0 = __floats2bfloat162_rn(v.x - __bfloat162float(h0.x), v.y - __bfloat162float(h0.y));
    __nv_bfloat162 e1 = __floats2bfloat162_rn(v.z - __bfloat162float(h1.x), v.w - __bfloat162float(h1.y));
    *(uint2*)(g_whi + idx) = make_uint2(b2u(h0), b2u(h1));
    *(uint2*)(g_wlo + idx) = make_uint2(b2u(e0), b2u(e1));
}

// ---------- full tensor-core GEMM (layers 0,1) ----------
#define GT_SMEM (3*30720)
template<int MODE>
__global__ __launch_bounds__(256) void gemm_tc(
        const __nv_bfloat16* __restrict__ Ahi, const __nv_bfloat16* __restrict__ Alo,
        const __nv_bfloat16* __restrict__ Whi, const __nv_bfloat16* __restrict__ Wlo,
        const float* __restrict__ bias,
        float* __restrict__ C, __nv_bfloat16* __restrict__ Chi, __nv_bfloat16* __restrict__ Clo,
        int M, int N, int K){
    extern __shared__ char sm[];
    uint32_t sb = smem_u32(sm);
    int tid = threadIdx.x, wid = tid>>5, lane = tid&31;
    int n0 = blockIdx.x*64, m0 = blockIdx.y*128;
    int z = blockIdx.z, nz = gridDim.z;
    int ks = K/nz, kbeg = z*ks, CH = ks/32;
    int wm = (wid>>1)*32, wn = (wid&1)*32;
    float acc[2][4][4];
#pragma unroll
    for (int a = 0; a < 2; a++)
#pragma unroll
        for (int b = 0; b < 4; b++)
#pragma unroll
            for (int c = 0; c < 4; c++) acc[a][b][c] = 0.f;
    uint32_t a_addr = (uint32_t)((wm + (lane&15))*80 + ((lane>>4)<<4));
    uint32_t b_addr = (uint32_t)(20480 + (wn + (lane&7) + ((lane>>4)<<3))*80 + ((lane&8)<<1));
    auto issue_stage = [&](int c){
        if (c < CH){
            uint32_t st = sb + (c%3)*30720;
            int kk = kbeg + c*32;
#pragma unroll
            for (int u = 0; u < 6; u++){
                int i = u*256 + tid;
                uint32_t dst; const __nv_bfloat16* src;
                if (i < 512){
                    int row = i>>2, qq = i&3;
                    dst = st + row*80 + qq*16;
                    src = Ahi + (size_t)(m0+row)*K + kk + qq*8;
                } else if (i < 1024){
                    int i2 = i-512, row = i2>>2, qq = i2&3;
                    dst = st + 10240 + row*80 + qq*16;
                    src = Alo + (size_t)(m0+row)*K + kk + qq*8;
                } else if (i < 1280){
                    int i2 = i-1024, row = i2>>2, qq = i2&3;
                    dst = st + 20480 + row*80 + qq*16;
                    src = Whi + (size_t)(n0+row)*K + kk + qq*8;
                } else {
                    int i2 = i-1280, row = i2>>2, qq = i2&3;
                    dst = st + 25600 + row*80 + qq*16;
                    src = Wlo + (size_t)(n0+row)*K + kk + qq*8;
                }
                cpa16(dst, src);
            }
        }
        CPA_COMMIT();
    };
    issue_stage(0); issue_stage(1); issue_stage(2);
    for (int c = 0; c < CH; c++){
        CPA_WAIT2();
        __syncthreads();
        uint32_t bufb = sb + (c%3)*30720;
#pragma unroll
        for (int s = 0; s < 2; s++){
            uint32_t ah[2][4], al[2][4], bh[2][4], bl[2][4];
            ldm4(ah[0], bufb + a_addr + s*32);
            ldm4(ah[1], bufb + a_addr + 16*80 + s*32);
            ldm4(al[0], bufb + a_addr + 10240 + s*32);
            ldm4(al[1], bufb + a_addr + 10240 + 16*80 + s*32);
            ldm4(bh[0], bufb + b_addr + s*32);
            ldm4(bh[1], bufb + b_addr + 16*80 + s*32);
            ldm4(bl[0], bufb + b_addr + 5120 + s*32);
            ldm4(bl[1], bufb + b_addr + 5120 + 16*80 + s*32);
#pragma unroll
            for (int mt = 0; mt < 2; mt++)
#pragma unroll
                for (int nf = 0; nf < 4; nf++){
                    const uint32_t* Bh = &bh[nf>>1][(nf&1)*2];
                    const uint32_t* Bl = &bl[nf>>1][(nf&1)*2];
                    mma_bf16(acc[mt][nf], ah[mt], Bh);
                    mma_bf16(acc[mt][nf], ah[mt], Bl);
                    mma_bf16(acc[mt][nf], al[mt], Bh);
                }
        }
        __syncthreads();
        issue_stage(c+3);
    }
#pragma unroll
    for (int mt = 0; mt < 2; mt++){
        int r0 = m0 + wm + mt*16 + (lane>>2);
#pragma unroll
        for (int nf = 0; nf < 4; nf++){
            int col = n0 + wn + nf*8 + (lane&3)*2;
            float v0 = acc[mt][nf][0], v1 = acc[mt][nf][1];
            float v2 = acc[mt][nf][2], v3 = acc[mt][nf][3];
            if (MODE == 0){
                size_t zo = (nz > 1) ? (size_t)z*M*N : 0;
                *(float2*)(C + zo + (size_t)r0*N + col)     = make_float2(v0, v1);
                *(float2*)(C + zo + (size_t)(r0+8)*N + col) = make_float2(v2, v3);
            } else {
                float b0 = bias[col], b1 = bias[col+1];
                v0 = gelu_f(v0 + b0); v1 = gelu_f(v1 + b1);
                v2 = gelu_f(v2 + b0); v3 = gelu_f(v3 + b1);
                __nv_bfloat162 h0 = __floats2bfloat162_rn(v0, v1);
                __nv_bfloat162 h2 = __floats2bfloat162_rn(v2, v3);
                __nv_bfloat162 l0 = __floats2bfloat162_rn(v0 - __bfloat162float(h0.x), v1 - __bfloat162float(h0.y));
                __nv_bfloat162 l2 = __floats2bfloat162_rn(v2 - __bfloat162float(h2.x), v3 - __bfloat162float(h2.y));
                *(uint32_t*)(Chi + (size_t)r0*N + col)     = b2u(h0);
                *(uint32_t*)(Chi + (size_t)(r0+8)*N + col) = b2u(h2);
                *(uint32_t*)(Clo + (size_t)r0*N + col)     = b2u(l0);
                *(uint32_t*)(Clo + (size_t)(r0+8)*N + col) = b2u(l2);
            }
        }
    }
}

// ---------- prep ----------
__global__ void init_buf_kernel(const float* __restrict__ hist){
    int idx = blockIdx.x*blockDim.x + threadIdx.x;
    if (idx >= 4*128*32) return;
    int i = idx & 31, t = (idx>>5)&127, b = idx>>12;
    g_buf[idx] = (t < 120) ? hist[(b*120 + t)*32 + i] : 0.0f;
}
__global__ void prep_pe_kernel(){
    int idx = blockIdx.x*blockDim.x + threadIdx.x;
    if (idx >= 128*512) return;
    int d = idx & 511, t = idx>>9;
    double freq = exp((double)(d & ~1) * (-9.210340371976184/512.0));
    double ang = (double)t * freq;
    g_pe[idx] = (float)((d & 1) ? cos(ang) : sin(ang));
}
__global__ __launch_bounds__(256) void prep_M_kernel(const float* __restrict__ Wr1,
        const float* __restrict__ W_emb, const float* __restrict__ b_emb,
        const float* __restrict__ br1){
    int j = blockIdx.x*8 + (threadIdx.x>>5);
    int lane = threadIdx.x&31;
    const float* wr = Wr1 + (size_t)j*1024;
    float a = 0.f;
    for (int k = 0; k < 512; k++) a = fmaf(wr[k], W_emb[k*32 + lane], a);
    g_M[lane*2048 + j] = a * EMB_SCALE;
    float c = 0.f;
    for (int k = lane; k < 512; k += 32) c = fmaf(wr[k], b_emb[k], c);
    c = warp_sum(c);
    if (lane == 0) g_c1[j] = c * EMB_SCALE + br1[j];
}

// ---------- embedding ----------
__global__ __launch_bounds__(512) void embed_kernel(const float* __restrict__ W_emb,
                                                    const float* __restrict__ b_emb){
    __shared__ float xs[32];
    int bt = blockIdx.x, t = bt & 127;
    if (threadIdx.x < 32) xs[threadIdx.x] = g_buf[bt*32 + threadIdx.x];
    __syncthreads();
    int d = threadIdx.x;
    const float* wr = W_emb + d*32;
    float acc = 0.f;
#pragma unroll
    for (int i = 0; i < 32; i++) acc = fmaf(wr[i], xs[i], acc);
    float y = (acc + b_emb[d]) * EMB_SCALE + g_pe[t*512 + d];
    g_h[bt*512 + d] = y;
    __nv_bfloat16 hi, lo; split_bf(y, hi, lo);
    g_hhi[bt*512 + d] = hi; g_hlo[bt*512 + d] = lo;
}

// ---------- full attention (layers 0,1) ----------
__global__ __launch_bounds__(256) void attn_kernel(){
    extern __shared__ float smf[];
    float* kt = smf;
    float* vs = kt + 64*129;
    float* qs = vs + 128*64;
    float* ws = qs + 32*64;
    const float* qp1 = g_qkv + 512*1536;
    int bh = blockIdx.x, b = bh>>3, h = bh&7;
    int q0 = blockIdx.y*32;
    int tid = threadIdx.x;
    for (int idx = tid; idx < 8192; idx += 256){
        int k = idx>>6, d = idx&63;
        int base = (b*128 + k)*1536 + h*64 + d;
        kt[d*129 + k] = g_qkv[base + 512] + qp1[base + 512];
        vs[k*64 + d]  = g_qkv[base + 1024] + qp1[base + 1024];
    }
    for (int idx = tid; idx < 2048; idx += 256){
        int r = idx>>6, d = idx&63;
        int base = (b*128 + q0 + r)*1536 + h*64 + d;
        qs[idx] = g_qkv[base] + qp1[base];
    }
    __syncthreads();
    int warp = tid>>5, lane = tid&31;
    int r0 = warp*4;
    float acc[4][4];
#pragma unroll
    for (int r = 0; r < 4; r++)
#pragma unroll
        for (int s = 0; s < 4; s++) acc[r][s] = 0.f;
#pragma unroll 4
    for (int d = 0; d < 64; d++){
        float k0v = kt[d*129 + lane];
        float k1v = kt[d*129 + 32 + lane];
        float k2v = kt[d*129 + 64 + lane];
        float k3v = kt[d*129 + 96 + lane];
#pragma unroll
        for (int r = 0; r < 4; r++){
            float qv = qs[(r0+r)*64 + d];
            acc[r][0] = fmaf(qv, k0v, acc[r][0]);
            acc[r][1] = fmaf(qv, k1v, acc[r][1]);
            acc[r][2] = fmaf(qv, k2v, acc[r][2]);
            acc[r][3] = fmaf(qv, k3v, acc[r][3]);
        }
    }
#pragma unroll
    for (int r = 0; r < 4; r++){
        int qi = q0 + r0 + r;
        float s[4];
#pragma unroll
        for (int sl = 0; sl < 4; sl++){
            int ki = sl*32 + lane;
            s[sl] = (ki > qi) ? acc[r][sl]*0.125f : NEGMIN;
        }
        float mx = warp_max(fmaxf(fmaxf(s[0], s[1]), fmaxf(s[2], s[3])));
        float e[4], sum = 0.f;
#pragma unroll
        for (int sl = 0; sl < 4; sl++){ e[sl] = expf(s[sl] - mx); sum += e[sl]; }
        sum = warp_sum(sum);
        float inv = 1.0f/sum;
#pragma unroll
        for (int sl = 0; sl < 4; sl++)
            ws[(warp*4 + r)*128 + sl*32 + lane] = e[sl]*inv;
    }
    __syncwarp();
    float o0[4] = {0,0,0,0}, o1[4] = {0,0,0,0};
#pragma unroll 4
    for (int k = 0; k < 128; k++){
        float v0 = vs[k*64 + lane];
        float v1 = vs[k*64 + 32 + lane];
#pragma unroll
        for (int r = 0; r < 4; r++){
            float wv = ws[(warp*4 + r)*128 + k];
            o0[r] = fmaf(wv, v0, o0[r]);
            o1[r] = fmaf(wv, v1, o1[r]);
        }
    }
#pragma unroll
    for (int r = 0; r < 4; r++){
        int row = (b*128 + q0 + r0 + r)*512 + h*64;
        __nv_bfloat16 hi, lo;
        split_bf(o0[r], hi, lo);
        g_athi[row + lane] = hi; g_atlo[row + lane] = lo;
        split_bf(o1[r], hi, lo);
        g_athi[row + 32 + lane] = hi; g_atlo[row + 32 + lane] = lo;
    }
}

// ---------- full LayerNorm ----------
__global__ __launch_bounds__(256) void ln_kernel(float* __restrict__ h,
        const float* __restrict__ parts, const float* __restrict__ bias,
        const float* __restrict__ gw, const float* __restrict__ bw){
    const int MN = 512*512;
    __shared__ float red[8];
    __shared__ float bc;
    int tid = threadIdx.x;
    int base = blockIdx.x*512;
    float x0 = h[base+tid]     + parts[base+tid]     + parts[MN+base+tid]
             + parts[2*MN+base+tid]     + parts[3*MN+base+tid];
    float x1 = h[base+tid+256] + parts[base+tid+256] + parts[MN+base+tid+256]
             + parts[2*MN+base+tid+256] + parts[3*MN+base+tid+256];
    if (bias){ x0 += bias[tid]; x1 += bias[tid+256]; }
    float s = warp_sum(x0 + x1);
    if ((tid&31) == 0) red[tid>>5] = s;
    __syncthreads();
    if (tid == 0){ float t = 0.f; for (int i = 0; i < 8; i++) t += red[i]; bc = t*(1.f/512.f); }
    __syncthreads();
    float mu = bc;
    float d0 = x0 - mu, d1 = x1 - mu;
    float v = warp_sum(d0*d0 + d1*d1);
    if ((tid&31) == 0) red[tid>>5] = v;
    __syncthreads();
    if (tid == 0){ float t = 0.f; for (int i = 0; i < 8; i++) t += red[i]; bc = rsqrtf(t*(1.f/512.f) + LN_EPS); }
    __syncthreads();
    float r = bc;
    float y0 = d0*r*gw[tid]     + bw[tid];
    float y1 = d1*r*gw[tid+256] + bw[tid+256];
    h[base+tid]     = y0;
    h[base+tid+256] = y1;
    __nv_bfloat16 hi, lo;
    split_bf(y0, hi, lo); g_hhi[base+tid] = hi;     g_hlo[base+tid] = lo;
    split_bf(y1, hi, lo); g_hhi[base+tid+256] = hi; g_hlo[base+tid+256] = lo;
}

// ======== persistent SMALL-PATH mega kernel (layers 2,3 + refine) ========
__device__ __forceinline__ void row_ln_w(size_t row, const float* __restrict__ bias,
        const float* __restrict__ gw2, const float* __restrict__ bw2, int lane){
    float xv[16]; float ls = 0.f;
#pragma unroll
    for (int j = 0; j < 16; j++){
        int c = lane + 32*j;
        float x = __ldcg(&g_h[row + c]) + __ldcg(&g_tmp[row + c]);
        if (bias) x += bias[c];
        xv[j] = x; ls += x;
    }
    float mu = warp_sum(ls) * (1.f/512.f);
    float lv = 0.f;
#pragma unroll
    for (int j = 0; j < 16; j++){ float d = xv[j]-mu; lv += d*d; }
    float rr = rsqrtf(warp_sum(lv)*(1.f/512.f) + LN_EPS);
#pragma unroll
    for (int j = 0; j < 16; j++){
        int c = lane + 32*j;
        g_h[row + c] = (xv[j]-mu)*rr*gw2[c] + bw2[c];
    }
}

__global__ __launch_bounds__(256) void small_mega(
        const float* __restrict__ Wq, const float* __restrict__ Wk,
        const float* __restrict__ Wv, const float* __restrict__ Wo,
        const float* __restrict__ ln1g, const float* __restrict__ ln1b,
        const float* __restrict__ W1, const float* __restrict__ b1,
        const float* __restrict__ W2, const float* __restrict__ b2,
        const float* __restrict__ ln2g, const float* __restrict__ ln2b,
        const float* __restrict__ Wr1, const float* __restrict__ Wr2,
        const float* __restrict__ br2, float* __restrict__ out, int step){
    __shared__ float shmem[4160];
    int tid = threadIdx.x, lane = tid&31, wid = tid>>5;
    int gw = blockIdx.x*8 + wid;
    int NW = gridDim.x*8;
    int gtid = blockIdx.x*256 + tid;
    int NT = gridDim.x*256;
    int q = 119 + step, nr = 9 - step;

    // s0: hbar[b][d]
    for (int i = gtid; i < 2048; i += NT){
        int b = i>>9, d = i&511;
        float s = 0.f;
        for (int t = 0; t < 128; t++) s += __ldcg(&g_h[(size_t)(b*128+t)*512 + d]);
        g_hbar[i] = s*(1.f/128.f);
    }
    grid_bar();
    // s1: vbar = Wv(layer2) @ hbar
    {
        const float* Wv2 = Wv + (size_t)2*262144;
        for (int i = gw; i < 2048; i += NW){
            int b = i>>9, c = i&511;
            const float4* w4 = (const float4*)(Wv2 + (size_t)c*512);
            const float4* h4 = (const float4*)(g_hbar + b*512);
            float a = 0.f;
#pragma unroll
            for (int j = 0; j < 4; j++){
                float4 ww = w4[lane+32*j];
                float4 hh = __ldcg(&h4[lane+32*j]);
                a = fmaf(ww.x,hh.x,a); a = fmaf(ww.y,hh.y,a);
                a = fmaf(ww.z,hh.z,a); a = fmaf(ww.w,hh.w,a);
            }
            a = warp_sum(a);
            if (lane == 0) g_vbar[b*512+c] = a;
        }
    }
    grid_bar();

    for (int l = 2; l < 4; l++){
        int np = (l == 2) ? nr : 1;
        int qc = np;
        const float* wq = Wq + (size_t)l*262144;
        const float* wk = Wk + (size_t)l*262144;
        const float* wv = Wv + (size_t)l*262144;
        const float* wo = Wo + (size_t)l*262144;
        const float* w1 = W1 + (size_t)l*1048576;
        const float* w2 = W2 + (size_t)l*1048576;
        const float* b1l = b1 + (size_t)l*2048;
        const float* b2l = b2 + (size_t)l*512;

        // qkv: 1536 cols, nr rows
        for (int i = gw; i < 1536; i += NW){
            const float* wrow = (i < 512) ? wq + (size_t)i*512
                              : (i < 1024) ? wk + (size_t)(i-512)*512
                              : wv + (size_t)(i-1024)*512;
            float4 wr[4];
#pragma unroll
            for (int j = 0; j < 4; j++) wr[j] = *(const float4*)(wrow + 4*(lane + 32*j));
            for (int b = 0; b < 4; b++)
                for (int r = 0; r < nr; r++){
                    size_t row = (size_t)(b*128 + q + r);
                    const float4* in4 = (const float4*)(g_h + row*512);
                    float a = 0.f;
#pragma unroll
                    for (int j = 0; j < 4; j++){
                        float4 h4 = __ldcg(&in4[lane + 32*j]);
                        a = fmaf(wr[j].x,h4.x,a); a = fmaf(wr[j].y,h4.y,a);
                        a = fmaf(wr[j].z,h4.z,a); a = fmaf(wr[j].w,h4.w,a);
                    }
                    a = warp_sum(a);
                    if (lane == 0) g_qkv[row*1536 + i] = a;
                }
        }
        grid_bar();
        // attn: blocks 0..31, one (b,h) each
        if (blockIdx.x < 32){
            float* ks = shmem;
            float* vs2 = shmem + 512;
            int b = blockIdx.x>>3, h = blockIdx.x&7;
            int nk = 127 - q;
            for (int i = tid; i < nk*64; i += 256){
                int j = i>>6, d = i&63;
                size_t base = (size_t)(b*128 + q + 1 + j)*1536 + h*64 + d;
                ks[j*64+d]  = __ldcg(&g_qkv[base + 512]);
                vs2[j*64+d] = __ldcg(&g_qkv[base + 1024]);
            }
            __syncthreads();
            for (int qi = wid; qi < qc; qi += 8){
                int p = q + qi;
                size_t orow = (size_t)(b*128+p)*512 + h*64;
                if (p == 127){
                    g_t2[orow + lane]      = __ldcg(&g_vbar[b*512 + h*64 + lane]);
                    g_t2[orow + 32 + lane] = __ldcg(&g_vbar[b*512 + h*64 + 32 + lane]);
                    continue;
                }
                float q0 = __ldcg(&g_qkv[(size_t)(b*128+p)*1536 + h*64 + lane]);
                float q1 = __ldcg(&g_qkv[(size_t)(b*128+p)*1536 + h*64 + 32 + lane]);
                float sc[8];
                float mx = -1e30f;
#pragma unroll
                for (int j = 0; j < 8; j++){
                    if (j >= qi && j < nk){
                        float s = warp_sum(q0*ks[j*64+lane] + q1*ks[j*64+32+lane]) * 0.125f;
                        sc[j] = s;
                        mx = fmaxf(mx, s);
                    } else sc[j] = -1e30f;
                }
                float e[8], sum = 0.f;
#pragma unroll
                for (int j = 0; j < 8; j++){
                    e[j] = (sc[j] > -1e29f) ? expf(sc[j] - mx) : 0.f;
                    sum += e[j];
                }
                float inv = 1.f/sum;
                float o0 = 0.f, o1 = 0.f;
#pragma unroll
                for (int j = 0; j < 8; j++){
                    o0 = fmaf(e[j]*inv, vs2[j*64+lane], o0);
                    o1 = fmaf(e[j]*inv, vs2[j*64+32+lane], o1);
                }
                g_t2[orow + lane] = o0;
                g_t2[orow + 32 + lane] = o1;
            }
        }
        grid_bar();
        // wo: 512 cols, np rows, In g_t2 (stride 512) -> g_tmp
        for (int i = gw; i < 512; i += NW){
            const float* wrow = wo + (size_t)i*512;
            float4 wr[4];
#pragma unroll
            for (int j = 0; j < 4; j++) wr[j] = *(const float4*)(wrow + 4*(lane + 32*j));
            for (int b = 0; b < 4; b++)
                for (int r = 0; r < np; r++){
                    size_t row = (size_t)(b*128 + q + r);
                    const float4* in4 = (const float4*)(g_t2 + row*512);
                    float a = 0.f;
#pragma unroll
                    for (int j = 0; j < 4; j++){
                        float4 h4 = __ldcg(&in4[lane + 32*j]);
                        a = fmaf(wr[j].x,h4.x,a); a = fmaf(wr[j].y,h4.y,a);
                        a = fmaf(wr[j].z,h4.z,a); a = fmaf(wr[j].w,h4.w,a);
                    }
                    a = warp_sum(a);
                    if (lane == 0) g_tmp[row*512 + i] = a;
                }
        }
        grid_bar();
        // ln1: warp per row
        for (int i = gw; i < 4*np; i += NW){
            int b = i/np, p = q + i%np;
            row_ln_w((size_t)(b*128+p)*512, nullptr, ln1g + l*512, ln1b + l*512, lane);
        }
        grid_bar();
        // ffn1: 2048 cols -> g_t2 stride 2048, gelu
        for (int i = gw; i < 2048; i += NW){
            const float* wrow = w1 + (size_t)i*512;
            float4 wr[4];
#pragma unroll
            for (int j = 0; j < 4; j++) wr[j] = *(const float4*)(wrow + 4*(lane + 32*j));
            float bv = b1l[i];
            for (int b = 0; b < 4; b++)
                for (int r = 0; r < np; r++){
                    size_t row = (size_t)(b*128 + q + r);
                    const float4* in4 = (const float4*)(g_h + row*512);
                    float a = 0.f;
#pragma unroll
                    for (int j = 0; j < 4; j++){
                        float4 h4 = __ldcg(&in4[lane + 32*j]);
                        a = fmaf(wr[j].x,h4.x,a); a = fmaf(wr[j].y,h4.y,a);
                        a = fmaf(wr[j].z,h4.z,a); a = fmaf(wr[j].w,h4.w,a);
                    }
                    a = warp_sum(a);
                    if (lane == 0) g_t2[row*2048 + i] = gelu_f(a + bv);
                }
        }
        grid_bar();
        // ffn2: 512 cols K=2048 -> g_tmp
        for (int i = gw; i < 512; i += NW){
            const float* wrow = w2 + (size_t)i*2048;
            float4 wr[16];
#pragma unroll
            for (int j = 0; j < 16; j++) wr[j] = *(const float4*)(wrow + 4*(lane + 32*j));
            for (int b = 0; b < 4; b++)
                for (int r = 0; r < np; r++){
                    size_t row = (size_t)(b*128 + q + r);
                    const float4* in4 = (const float4*)(g_t2 + row*2048);
                    float a = 0.f;
#pragma unroll
                    for (int j = 0; j < 16; j++){
                        float4 h4 = __ldcg(&in4[lane + 32*j]);
                        a = fmaf(wr[j].x,h4.x,a); a = fmaf(wr[j].y,h4.y,a);
                        a = fmaf(wr[j].z,h4.z,a); a = fmaf(wr[j].w,h4.w,a);
                    }
                    a = warp_sum(a);
                    if (lane == 0) g_tmp[row*512 + i] = a;
                }
        }
        grid_bar();
        // ln2
        for (int i = gw; i < 4*np; i += NW){
            int b = i/np, p = q + i%np;
            row_ln_w((size_t)(b*128+p)*512, b2l, ln2g + l*512, ln2b + l*512, lane);
        }
        grid_bar();
    }
    // refine basev: 4 batches x 2048 j
    for (int i = gw; i < 8192; i += NW){
        int b = i>>11, j = i&2047;
        const float* wr = Wr1 + (size_t)j*1024 + 512;
        size_t row = (size_t)(b*128+q)*512;
        float a = 0.f;
        for (int k = lane; k < 512; k += 32) a = fmaf(wr[k], __ldcg(&g_h[row+k]), a);
        a = warp_sum(a);
        if (lane == 0) g_basev[b*2048 + j] = a + g_c1[j];
    }
    grid_bar();
    // refine iter: blocks 0..3
    if (blockIdx.x < 4){
        int b = blockIdx.x;
        float* cur = shmem;
        float* basev_s = shmem + 32;
        float* hid = shmem + 2080;
        float* outp = shmem + 4128;
        int rowp = b*128 + q;
        for (int i = tid; i < 2048; i += 256) basev_s[i] = __ldcg(&g_basev[b*2048 + i]);
        if (tid < 32) cur[tid] = __ldcg(&g_buf[rowp*32 + tid]);
        __syncthreads();
        for (int it = 0; it < 5; it++){
#pragma unroll
            for (int c = 0; c < 8; c++){
                int j = c*256 + tid;
                float p = basev_s[j];
#pragma unroll
                for (int k = 0; k < 32; k++) p = fmaf(g_M[k*2048 + j], cur[k], p);
                hid[j] = gelu_f(p);
            }
            __syncthreads();
#pragma unroll
            for (int ii = 0; ii < 4; ii++){
                int i = wid*4 + ii;
                const float* w2r = Wr2 + (size_t)i*2048;
                float p = 0.f;
#pragma unroll 8
                for (int k = lane; k < 2048; k += 32) p = fmaf(w2r[k], hid[k], p);
                p = warp_sum(p);
                if (lane == 0) outp[i] = p;
            }
            __syncthreads();
            if (tid < 32) cur[tid] += outp[tid] + br2[tid];
            __syncthreads();
        }
        if (tid < 32){
            float v = cur[tid];
            g_buf[(rowp+1)*32 + tid] = v;
            out[(b*8 + step)*32 + tid] = v;
        }
    }
}

// ---------- host ----------
#define ATTN_SMEM (22592*4)

extern "C" void kernel_launch(void* const* d_in, const int* in_sizes, int n_in,
                              void* d_out, int out_size){
    const float* hist  = (const float*)d_in[0];
    const float* W_emb = (const float*)d_in[2];
    const float* b_emb = (const float*)d_in[3];
    const float* Wq    = (const float*)d_in[4];
    const float* Wk    = (const float*)d_in[5];
    const float* Wv    = (const float*)d_in[6];
    const float* Wo    = (const float*)d_in[7];
    const float* ln1g  = (const float*)d_in[8];
    const float* ln1b  = (const float*)d_in[9];
    const float* W1    = (const float*)d_in[10];
    const float* b1    = (const float*)d_in[11];
    const float* W2    = (const float*)d_in[12];
    const float* b2    = (const float*)d_in[13];
    const float* ln2g  = (const float*)d_in[14];
    const float* ln2b  = (const float*)d_in[15];
    const float* Wr1   = (const float*)d_in[16];
    const float* br1   = (const float*)d_in[17];
    const float* Wr2   = (const float*)d_in[18];
    const float* br2   = (const float*)d_in[19];
    float* out = (float*)d_out;

    cudaFuncSetAttribute(attn_kernel, cudaFuncAttributeMaxDynamicSharedMemorySize, ATTN_SMEM);
    cudaFuncSetAttribute(gemm_tc<0>, cudaFuncAttributeMaxDynamicSharedMemorySize, GT_SMEM);
    cudaFuncSetAttribute(gemm_tc<1>, cudaFuncAttributeMaxDynamicSharedMemorySize, GT_SMEM);

    float *ph, *pqkv, *pt2;
    __nv_bfloat16 *pwhi, *pwlo, *phhi, *phlo, *pathi, *patlo, *pffhi, *pfflo;
    cudaGetSymbolAddress((void**)&ph,    g_h);
    cudaGetSymbolAddress((void**)&pqkv,  g_qkv);
    cudaGetSymbolAddress((void**)&pt2,   g_t2);
    cudaGetSymbolAddress((void**)&pwhi,  g_whi);
    cudaGetSymbolAddress((void**)&pwlo,  g_wlo);
    cudaGetSymbolAddress((void**)&phhi,  g_hhi);
    cudaGetSymbolAddress((void**)&phlo,  g_hlo);
    cudaGetSymbolAddress((void**)&pathi, g_athi);
    cudaGetSymbolAddress((void**)&patlo, g_atlo);
    cudaGetSymbolAddress((void**)&pffhi, g_ffhi);
    cudaGetSymbolAddress((void**)&pfflo, g_fflo);

    init_buf_kernel<<<(4*128*32 + 255)/256, 256>>>(hist);
    split_weights_kernel<<<6144, 256>>>(Wq, Wk, Wv, Wo, W1, W2);
    prep_pe_kernel<<<(128*512 + 255)/256, 256>>>();
    prep_M_kernel<<<256, 256>>>(Wr1, W_emb, b_emb, br1);

    for (int step = 0; step < 8; step++){
        embed_kernel<<<512, 512>>>(W_emb, b_emb);
        for (int l = 0; l < 2; l++){
            size_t LB = (size_t)l*3145728;
            gemm_tc<0><<<dim3(24,4,2), 256, GT_SMEM>>>(phhi, phlo, pwhi+LB, pwlo+LB,
                    nullptr, pqkv, nullptr, nullptr, 512, 1536, 512);
            attn_kernel<<<dim3(32,4), 256, ATTN_SMEM>>>();
            gemm_tc<0><<<dim3(8,4,4), 256, GT_SMEM>>>(pathi, patlo, pwhi+LB+786432, pwlo+LB+786432,
                    nullptr, pt2, nullptr, nullptr, 512, 512, 512);
            ln_kernel<<<512, 256>>>(ph, pt2, nullptr, ln1g + l*512, ln1b + l*512);
            gemm_tc<1><<<dim3(32,4,1), 256, GT_SMEM>>>(phhi, phlo, pwhi+LB+1048576, pwlo+LB+1048576,
                    b1 + l*2048, nullptr, pffhi, pfflo, 512, 2048, 512);
            gemm_tc<0><<<dim3(8,4,4), 256, GT_SMEM>>>(pffhi, pfflo, pwhi+LB+2097152, pwlo+LB+2097152,
                    nullptr, pt2, nullptr, nullptr, 512, 512, 2048);
            ln_kernel<<<512, 256>>>(ph, pt2, b2 + l*512, ln2g + l*512, ln2b + l*512);
        }
        small_mega<<<128, 256>>>(Wq, Wk, Wv, Wo, ln1g, ln1b, W1, b1, W2, b2,
                                 ln2g, ln2b, Wr1, Wr2, br2, out, step);
    }
}